// round 3
// baseline (speedup 1.0000x reference)
#include <cuda_runtime.h>
#include <math.h>

#define H   128
#define P   512
#define B   32
#define G4  512
#define KK  65536
#define SPLITS 148          // = SM count: 592 blocks = exactly 4 CTAs/SM, one wave
#define KT  64
#define JT  128

// -------- scratch (no allocations allowed) --------
__device__ float g_fb[B * H];                 // 16 KB
__device__ float g_scores[B * P];             // 64 KB
__device__ float g_beta[B * P];               // 64 KB
__device__ float g_xT[KK * B];                // 8 MB   xT[k][b] = beta[b][p]*H_r[p,b,h], k=p*H+h
__device__ float g_partial[SPLITS * B * G4];  // 9.7 MB partial[s][b][j]

__device__ __forceinline__ void ffma2(unsigned long long& d, unsigned long long a, unsigned long long b) {
    asm("fma.rn.f32x2 %0, %1, %2, %0;" : "+l"(d) : "l"(a), "l"(b));
}
__device__ __forceinline__ float sigm(float x) { return 1.f / (1.f + expf(-x)); }

// ============================================================
// K0: fb[b][k] = b_f[k] + sum_h W_f[k,h] * h_ak[b,h]
// ============================================================
__global__ void k_fb(const float* __restrict__ h_ak, const float* __restrict__ W_f,
                     const float* __restrict__ b_f) {
    __shared__ float ha[H];
    int b = blockIdx.x, k = threadIdx.x;
    ha[k] = h_ak[b * H + k];
    __syncthreads();
    const float4* wr = (const float4*)(W_f + k * H);
    float s = b_f[k];
#pragma unroll
    for (int i = 0; i < H / 4; i++) {
        float4 w = wr[i];
        s += w.x * ha[4 * i] + w.y * ha[4 * i + 1] + w.z * ha[4 * i + 2] + w.w * ha[4 * i + 3];
    }
    g_fb[b * H + k] = s;
}

// ============================================================
// A1: per-p block: fa[b][k] = sum_h Hr[p,b,h]*W_fn[k,h]
//     scores[b][p] = sum_k beta_w[k]*tanh(fa+fb) + beta_b
// f32x2 inner loop; deterministic shared reduction.
// ============================================================
#define A1_HD_OFF 67584              // Wt: 128*132*4 = 67584 bytes
#define A1_BW_OFF 100352             // Hd: 128*32*8 = 32768
#define A1_SR_OFF 100864             // bw: 512
#define A1_SMEM   103040             // sred: 32*17*4 = 2176

__global__ __launch_bounds__(128) void k_scores(const float* __restrict__ Hr,
                                                const float* __restrict__ W_fn,
                                                const float* __restrict__ beta_w,
                                                const float* __restrict__ beta_b) {
    extern __shared__ char sm[];
    float* Wt = (float*)(sm);                                      // [128][132] (k-transposed)
    unsigned long long* Hd = (unsigned long long*)(sm + A1_HD_OFF); // [128][32] dup pairs
    float* bw = (float*)(sm + A1_BW_OFF);
    float* sred = (float*)(sm + A1_SR_OFF);                        // [32][17]
    float* Hs = (float*)(sm);                                      // tmp [32][129], aliases Wt

    int p = blockIdx.x, tid = threadIdx.x;
    const float* hr = Hr + (size_t)p * (B * H);

    // stage 1: Hr[p] -> Hs[b][h]  (coalesced load, pad-129 conflict-free store)
#pragma unroll
    for (int r = 0; r < B; r++) Hs[r * 129 + tid] = hr[r * H + tid];
    __syncthreads();

    // stage 2: Hd[h][b] = (v,v)
    float2* Hd2 = (float2*)Hd;
#pragma unroll
    for (int r = 0; r < 32; r++) {
        int e = tid + r * 128;
        int h = e >> 5, b = e & 31;
        float v = Hs[b * 129 + h];
        Hd2[h * 32 + b] = make_float2(v, v);
    }
    __syncthreads();

    // stage 3: Wt[h][k] = W_fn[k][h]  (overwrites Hs region)
    bw[tid] = beta_w[tid];
#pragma unroll 4
    for (int r = 0; r < 128; r++) Wt[tid * 132 + r] = W_fn[r * 128 + tid];
    __syncthreads();

    int kg = tid & 15, bg = tid >> 4;      // 16 k-groups of 8, 8 b-groups of 4
    unsigned long long acc[4][4];          // [bi][k-pair m]
#pragma unroll
    for (int i = 0; i < 4; i++)
#pragma unroll
        for (int m = 0; m < 4; m++) acc[i][m] = 0ull;

#pragma unroll 4
    for (int h = 0; h < H; h++) {
        ulonglong2 wA = *(const ulonglong2*)(Wt + h * 132 + kg * 8);
        ulonglong2 wB = *(const ulonglong2*)(Wt + h * 132 + kg * 8 + 4);
        ulonglong2 hA = *(const ulonglong2*)(Hd + h * 32 + bg * 4);
        ulonglong2 hB = *(const ulonglong2*)(Hd + h * 32 + bg * 4 + 2);
        ffma2(acc[0][0], wA.x, hA.x); ffma2(acc[0][1], wA.y, hA.x);
        ffma2(acc[0][2], wB.x, hA.x); ffma2(acc[0][3], wB.y, hA.x);
        ffma2(acc[1][0], wA.x, hA.y); ffma2(acc[1][1], wA.y, hA.y);
        ffma2(acc[1][2], wB.x, hA.y); ffma2(acc[1][3], wB.y, hA.y);
        ffma2(acc[2][0], wA.x, hB.x); ffma2(acc[2][1], wA.y, hB.x);
        ffma2(acc[2][2], wB.x, hB.x); ffma2(acc[2][3], wB.y, hB.x);
        ffma2(acc[3][0], wA.x, hB.y); ffma2(acc[3][1], wA.y, hB.y);
        ffma2(acc[3][2], wB.x, hB.y); ffma2(acc[3][3], wB.y, hB.y);
    }

    // epilogue: tanh + beta_w dot, deterministic two-level reduce
#pragma unroll
    for (int bi = 0; bi < 4; bi++) {
        int b = bg * 4 + bi;
        const float* fbr = g_fb + b * H + kg * 8;
        float s = 0.f;
#pragma unroll
        for (int m = 0; m < 4; m++) {
            float2 v = *(float2*)&acc[bi][m];
            int k0 = kg * 8 + 2 * m;
            s += bw[k0]     * tanhf(v.x + fbr[2 * m]);
            s += bw[k0 + 1] * tanhf(v.y + fbr[2 * m + 1]);
        }
        sred[b * 17 + kg] = s;
    }
    __syncthreads();
    if (tid < 32) {
        float s = 0.f;
#pragma unroll
        for (int i = 0; i < 16; i++) s += sred[tid * 17 + i];
        g_scores[tid * P + p] = s + beta_b[0];
    }
}

// ============================================================
// A2: softmax over P per b; writes beta (scratch) + logp (output)
// ============================================================
__global__ __launch_bounds__(512) void k_softmax(float* __restrict__ out_logp) {
    __shared__ float red[512];
    int b = blockIdx.x, pp = threadIdx.x;
    float v = g_scores[b * P + pp];
    red[pp] = v;
    __syncthreads();
    for (int s = 256; s > 0; s >>= 1) {
        if (pp < s) red[pp] = fmaxf(red[pp], red[pp + s]);
        __syncthreads();
    }
    float m = red[0];
    __syncthreads();
    float e = expf(v - m);
    red[pp] = e;
    __syncthreads();
    for (int s = 256; s > 0; s >>= 1) {
        if (pp < s) red[pp] += red[pp + s];
        __syncthreads();
    }
    float sum = red[0];
    g_beta[b * P + pp] = e / sum;
    out_logp[b * P + pp] = (v - m) - logf(sum);
}

// ============================================================
// A3: xT[p*H+h][b] = beta[b][p] * Hr[p,b,h]  (transpose via smem)
// ============================================================
__global__ __launch_bounds__(128) void k_buildx(const float* __restrict__ Hr) {
    __shared__ float Hs[32 * 129];
    __shared__ float bs[32];
    int p = blockIdx.x, tid = threadIdx.x;
    const float* hr = Hr + (size_t)p * (B * H);
#pragma unroll
    for (int r = 0; r < B; r++) Hs[r * 129 + tid] = hr[r * H + tid];
    if (tid < 32) bs[tid] = g_beta[tid * P + p];
    __syncthreads();
    float* xp = g_xT + (size_t)p * (B * H);
#pragma unroll
    for (int r = 0; r < 32; r++) {
        int e = tid + r * 128;
        int h = e >> 5, b = e & 31;
        xp[e] = Hs[b * 129 + h] * bs[b];
    }
}

// ============================================================
// G: split-K GEMM  partial[s][b][j] = sum_{k in chunk} W_ih[j,k]*xT[k][b]
// 592 blocks (148 splits x 4 j-tiles) = exactly 4 CTAs/SM, one wave.
// 1024 stages of KT=64: splits 0..135 take 7 stages, 136..147 take 6.
// ============================================================
__global__ __launch_bounds__(256) void k_gemm(const float* __restrict__ W_ih) {
    __shared__ __align__(16) float Ws[KT * JT];               // [k][j] 32 KB
    __shared__ __align__(16) unsigned long long Xd[KT * B];   // [k][b] dup pairs 16 KB
    int split = blockIdx.x, jt = blockIdx.y;
    int tid = threadIdx.x;
    // balanced stage assignment: 136*7 + 12*6 = 1024
    int s0, ns;
    if (split < 136) { s0 = split * 7; ns = 7; }
    else             { s0 = 952 + (split - 136) * 6; ns = 6; }

    int jrow = tid >> 1;
    int kh = (tid & 1) * 8;                   // float4 half-offset within 64-float row
    const float* wrow = W_ih + (size_t)(jt * JT + jrow) * KK;
    int bq = tid & 7, jq = tid >> 3;
    unsigned long long acc[2][4];
#pragma unroll
    for (int i = 0; i < 2; i++)
#pragma unroll
        for (int m = 0; m < 4; m++) acc[i][m] = 0ull;
    float2* Xd2 = (float2*)Xd;

    for (int st = 0; st < ns; st++) {
        int g = s0 + st;                       // global stage, k-range [g*64, g*64+64)
        const float4* wsrc = (const float4*)(wrow + g * KT) + kh;
#pragma unroll
        for (int i = 0; i < 8; i++) {
            float4 v = wsrc[i];
            int kk = (kh + i) * 4;
            Ws[(kk + 0) * JT + jrow] = v.x;
            Ws[(kk + 1) * JT + jrow] = v.y;
            Ws[(kk + 2) * JT + jrow] = v.z;
            Ws[(kk + 3) * JT + jrow] = v.w;
        }
        const float* xsrc = g_xT + (size_t)g * KT * B;
#pragma unroll
        for (int r = 0; r < 8; r++) {
            int e = tid + r * 256;
            float v = xsrc[e];
            Xd2[e] = make_float2(v, v);
        }
        __syncthreads();
#pragma unroll
        for (int k = 0; k < KT; k++) {
            ulonglong2 w2 = *(const ulonglong2*)(Ws + k * JT + jq * 4);   // (j0,j1),(j2,j3)
            ulonglong2 xa = *(const ulonglong2*)(Xd + k * B + bq * 4);    // dup(b0),dup(b1)
            ulonglong2 xb = *(const ulonglong2*)(Xd + k * B + bq * 4 + 2);
            ffma2(acc[0][0], w2.x, xa.x); ffma2(acc[1][0], w2.y, xa.x);
            ffma2(acc[0][1], w2.x, xa.y); ffma2(acc[1][1], w2.y, xa.y);
            ffma2(acc[0][2], w2.x, xb.x); ffma2(acc[1][2], w2.y, xb.x);
            ffma2(acc[0][3], w2.x, xb.y); ffma2(acc[1][3], w2.y, xb.y);
        }
        __syncthreads();
    }
#pragma unroll
    for (int bi = 0; bi < 4; bi++) {
        int b = bq * 4 + bi;
        float2 lo = *(float2*)&acc[0][bi];
        float2 hi = *(float2*)&acc[1][bi];
        float4 o = make_float4(lo.x, lo.y, hi.x, hi.y);
        *(float4*)(g_partial + (size_t)(split * B + b) * G4 + jt * JT + jq * 4) = o;
    }
}

// ============================================================
// F: reduce partials + bias + W_hh term, LSTM nonlinearity
// unroll 8 -> MLP~8 on the 148-deep latency chain (only 32 CTAs resident)
// ============================================================
__global__ __launch_bounds__(512) void k_final(const float* __restrict__ h_ak,
                                               const float* __restrict__ hidden,
                                               const float* __restrict__ W_hh,
                                               const float* __restrict__ b_ih,
                                               const float* __restrict__ b_hh,
                                               float* __restrict__ out) {
    __shared__ float ha[H];
    __shared__ float gs[G4];
    int b = blockIdx.x, j = threadIdx.x;
    if (j < H) ha[j] = h_ak[b * H + j];
    __syncthreads();
    const float* pp = g_partial + (size_t)b * G4 + j;
    float g = b_ih[j] + b_hh[j];
    float a0 = 0.f, a1 = 0.f, a2 = 0.f, a3 = 0.f;
#pragma unroll 2
    for (int s = 0; s < SPLITS - (SPLITS % 4); s += 4) {
        a0 += pp[(size_t)(s + 0) * B * G4];
        a1 += pp[(size_t)(s + 1) * B * G4];
        a2 += pp[(size_t)(s + 2) * B * G4];
        a3 += pp[(size_t)(s + 3) * B * G4];
    }
    g += a0 + a1 + a2 + a3;
    g += pp[(size_t)(SPLITS - 0) * B * G4 - (size_t)B * G4 * 0] * 0.f; // no-op keep shape
    // handle tail (SPLITS % 4 == 0 for 148, but keep generic)
#if (SPLITS % 4) != 0
    for (int s = SPLITS - (SPLITS % 4); s < SPLITS; s++) g += pp[(size_t)s * B * G4];
#endif
    const float4* wh = (const float4*)(W_hh + j * H);
#pragma unroll
    for (int q = 0; q < H / 4; q++) {
        float4 w = wh[q];
        g += w.x * ha[4 * q] + w.y * ha[4 * q + 1] + w.z * ha[4 * q + 2] + w.w * ha[4 * q + 3];
    }
    gs[j] = g;
    __syncthreads();
    if (j < H) {
        float gi = gs[j], gf = gs[H + j], gg = gs[2 * H + j], go = gs[3 * H + j];
        float c = sigm(gf) * hidden[b * H + j] + sigm(gi) * tanhf(gg);
        float hn = sigm(go) * tanhf(c);
        out[b * H + j] = hn;           // h_new
        out[B * H + b * H + j] = c;    // c_new
    }
}

// ============================================================
extern "C" void kernel_launch(void* const* d_in, const int* in_sizes, int n_in,
                              void* d_out, int out_size) {
    const float* h_ak   = (const float*)d_in[0];
    const float* H_r    = (const float*)d_in[1];
    const float* hidden = (const float*)d_in[2];
    const float* W_f    = (const float*)d_in[3];
    const float* b_f    = (const float*)d_in[4];
    const float* W_fn   = (const float*)d_in[5];
    const float* beta_w = (const float*)d_in[6];
    const float* beta_b = (const float*)d_in[7];
    const float* W_ih   = (const float*)d_in[8];
    const float* W_hh   = (const float*)d_in[9];
    const float* b_ih   = (const float*)d_in[10];
    const float* b_hh   = (const float*)d_in[11];
    float* out = (float*)d_out;

    cudaFuncSetAttribute(k_scores, cudaFuncAttributeMaxDynamicSharedMemorySize, A1_SMEM);

    k_fb<<<B, H>>>(h_ak, W_f, b_f);
    k_scores<<<P, 128, A1_SMEM>>>(H_r, W_fn, beta_w, beta_b);
    k_softmax<<<B, P>>>(out + 2 * B * H);
    k_buildx<<<P, 128>>>(H_r);
    k_gemm<<<dim3(SPLITS, 4), 256>>>(W_ih);
    k_final<<<B, G4>>>(h_ak, hidden, W_hh, b_ih, b_hh, out);
    (void)in_sizes; (void)n_in; (void)out_size;
}

// round 8
// speedup vs baseline: 1.1234x; 1.1234x over previous
#include <cuda_runtime.h>
#include <math.h>

#define H   128
#define P   512
#define B   32
#define G4  512
#define KK  65536
#define SPLITS 148          // 592 blocks = exactly 4 CTAs x 148 SMs, one wave
#define KT  32
#define JT  128

// -------- scratch (no allocations allowed) --------
__device__ float g_fb[B * H];                 // 16 KB
__device__ float g_WfnT[H * H];               // 64 KB  W_fn^T [h][k]
__device__ float g_scores[B * P];             // 64 KB
__device__ float g_beta[B * P];               // 64 KB
__device__ float g_xT[KK * B];                // 8 MB   xT[k][b]
__device__ float g_partial[SPLITS * G4 * B];  // 9.7 MB partial[s][j][b]  (b-major, coalesced)

__device__ __forceinline__ void ffma2(unsigned long long& d, unsigned long long a, unsigned long long b) {
    asm("fma.rn.f32x2 %0, %1, %2, %0;" : "+l"(d) : "l"(a), "l"(b));
}
__device__ __forceinline__ float sigm(float x) { return 1.f / (1.f + expf(-x)); }

// ============================================================
// PREP: blocks 0..31: fb[b][k] = b_f[k] + W_f[k,:]·h_ak[b,:]
//       blocks 32..47: W_fnT[h][k] = W_fn[k][h]  (8 h-rows each)
// ============================================================
__global__ __launch_bounds__(128) void k_prep(const float* __restrict__ h_ak,
                                              const float* __restrict__ W_f,
                                              const float* __restrict__ b_f,
                                              const float* __restrict__ W_fn) {
    __shared__ float sbuf[128 * 9];
    int tid = threadIdx.x;
    if (blockIdx.x < 32) {
        int b = blockIdx.x;
        float* ha = sbuf;
        ha[tid] = h_ak[b * H + tid];
        __syncthreads();
        const float4* wr = (const float4*)(W_f + tid * H);
        float s = b_f[tid];
#pragma unroll
        for (int i = 0; i < H / 4; i++) {
            float4 w = wr[i];
            s += w.x * ha[4 * i] + w.y * ha[4 * i + 1] + w.z * ha[4 * i + 2] + w.w * ha[4 * i + 3];
        }
        g_fb[b * H + tid] = s;
    } else {
        int bt = blockIdx.x - 32;          // h-range [bt*8, bt*8+8)
#pragma unroll
        for (int hh = 0; hh < 8; hh++)
            sbuf[tid * 9 + hh] = W_fn[tid * H + bt * 8 + hh];
        __syncthreads();
#pragma unroll
        for (int hh = 0; hh < 8; hh++)
            g_WfnT[(bt * 8 + hh) * H + tid] = sbuf[tid * 9 + hh];
    }
}

// ============================================================
// A1: scores. 256 blocks x 128 thr, 2 p's per block (one occ-2 wave).
// ============================================================
#define WT_STRIDE 136
#define OFF_HD 69632              // Wt: 128*136*4
#define OFF_BW 102400             // Hd: 128*32*8 = 32768
#define OFF_SR 102912             // bw: 512
#define A1_SMEM 105088            // sred: 32*17*4 = 2176

__global__ __launch_bounds__(128) void k_scores(const float* __restrict__ Hr,
                                                const float* __restrict__ beta_w,
                                                const float* __restrict__ beta_b) {
    extern __shared__ char sm[];
    float* Wt = (float*)(sm);                                       // [128][136]
    unsigned long long* Hd = (unsigned long long*)(sm + OFF_HD);    // [128][32] dup
    float* bw = (float*)(sm + OFF_BW);
    float* sred = (float*)(sm + OFF_SR);                            // [32][17]
    float* Hs = (float*)(sm);                                       // tmp [32][129] aliases Wt front

    int tid = threadIdx.x;
    bw[tid] = beta_w[tid];
    int kg = tid & 15, bg = tid >> 4;

    for (int pi = 0; pi < 2; pi++) {
        int p = blockIdx.x * 2 + pi;
        const float* hr = Hr + (size_t)p * (B * H);
        __syncthreads();   // previous-iteration readers done before Hs overwrite
#pragma unroll
        for (int r = 0; r < B; r++) Hs[r * 129 + tid] = hr[r * H + tid];
        __syncthreads();
        float2* Hd2 = (float2*)Hd;
#pragma unroll
        for (int r = 0; r < 32; r++) {
            int e = tid + r * 128;
            int h = e >> 5, b = e & 31;
            float v = Hs[b * 129 + h];
            Hd2[h * 32 + b] = make_float2(v, v);
        }
        __syncthreads();
#pragma unroll 4
        for (int r = 0; r < 128; r++) Wt[r * WT_STRIDE + tid] = g_WfnT[r * H + tid];
        __syncthreads();

        unsigned long long acc[4][4];
#pragma unroll
        for (int i = 0; i < 4; i++)
#pragma unroll
            for (int m = 0; m < 4; m++) acc[i][m] = 0ull;

#pragma unroll 4
        for (int h = 0; h < H; h++) {
            ulonglong2 wA = *(const ulonglong2*)(Wt + h * WT_STRIDE + kg * 8);
            ulonglong2 wB = *(const ulonglong2*)(Wt + h * WT_STRIDE + kg * 8 + 4);
            ulonglong2 hA = *(const ulonglong2*)(Hd + h * 32 + bg * 4);
            ulonglong2 hB = *(const ulonglong2*)(Hd + h * 32 + bg * 4 + 2);
            ffma2(acc[0][0], wA.x, hA.x); ffma2(acc[0][1], wA.y, hA.x);
            ffma2(acc[0][2], wB.x, hA.x); ffma2(acc[0][3], wB.y, hA.x);
            ffma2(acc[1][0], wA.x, hA.y); ffma2(acc[1][1], wA.y, hA.y);
            ffma2(acc[1][2], wB.x, hA.y); ffma2(acc[1][3], wB.y, hA.y);
            ffma2(acc[2][0], wA.x, hB.x); ffma2(acc[2][1], wA.y, hB.x);
            ffma2(acc[2][2], wB.x, hB.x); ffma2(acc[2][3], wB.y, hB.x);
            ffma2(acc[3][0], wA.x, hB.y); ffma2(acc[3][1], wA.y, hB.y);
            ffma2(acc[3][2], wB.x, hB.y); ffma2(acc[3][3], wB.y, hB.y);
        }

#pragma unroll
        for (int bi = 0; bi < 4; bi++) {
            int b = bg * 4 + bi;
            const float* fbr = g_fb + b * H + kg * 8;
            float s = 0.f;
#pragma unroll
            for (int m = 0; m < 4; m++) {
                float2 v = *(float2*)&acc[bi][m];
                int k0 = kg * 8 + 2 * m;
                s += bw[k0]     * tanhf(v.x + fbr[2 * m]);
                s += bw[k0 + 1] * tanhf(v.y + fbr[2 * m + 1]);
            }
            sred[b * 17 + kg] = s;
        }
        __syncthreads();
        if (tid < 32) {
            float s = 0.f;
#pragma unroll
            for (int i = 0; i < 16; i++) s += sred[tid * 17 + i];
            g_scores[tid * P + p] = s + beta_b[0];
        }
    }
}

// ============================================================
// A2: softmax over P per b; beta (scratch) + logp (output)
// ============================================================
__global__ __launch_bounds__(512) void k_softmax(float* __restrict__ out_logp) {
    __shared__ float red[512];
    int b = blockIdx.x, pp = threadIdx.x;
    float v = g_scores[b * P + pp];
    red[pp] = v;
    __syncthreads();
    for (int s = 256; s > 0; s >>= 1) {
        if (pp < s) red[pp] = fmaxf(red[pp], red[pp + s]);
        __syncthreads();
    }
    float m = red[0];
    __syncthreads();
    float e = expf(v - m);
    red[pp] = e;
    __syncthreads();
    for (int s = 256; s > 0; s >>= 1) {
        if (pp < s) red[pp] += red[pp + s];
        __syncthreads();
    }
    float sum = red[0];
    g_beta[b * P + pp] = e / sum;
    out_logp[b * P + pp] = (v - m) - logf(sum);
}

// ============================================================
// A3: xT[p*H+h][b] = beta[b][p] * Hr[p,b,h]  (256 thr, more MLP)
// ============================================================
__global__ __launch_bounds__(256) void k_buildx(const float* __restrict__ Hr) {
    __shared__ float Hs[32 * 129];
    __shared__ float bs[32];
    int p = blockIdx.x, tid = threadIdx.x;
    const float* hr = Hr + (size_t)p * (B * H);
#pragma unroll
    for (int it = 0; it < 16; it++) {
        int idx = tid + it * 256;
        Hs[(idx >> 7) * 129 + (idx & 127)] = hr[idx];
    }
    if (tid < 32) bs[tid] = g_beta[tid * P + p];
    __syncthreads();
    float* xp = g_xT + (size_t)p * (B * H);
#pragma unroll
    for (int r = 0; r < 16; r++) {
        int e = tid + r * 256;
        int h = e >> 5, b = e & 31;
        xp[e] = Hs[b * 129 + h] * bs[b];
    }
}

// ============================================================
// G: split-K GEMM, software-pipelined (register-staged prefetch).
// 592 blocks (148 x 4 jt), 256 thr, 4 CTAs/SM, one wave.
// 2048 stages of KT=32: splits 0..135 take 14, 136..147 take 12.
// Output: partial[s][j][b]  (warp stores coalesced b-major)
// ============================================================
__global__ __launch_bounds__(256, 4) void k_gemm(const float* __restrict__ W_ih) {
    __shared__ __align__(16) float Ws[KT * JT];               // 16 KB [k][j]
    __shared__ __align__(16) unsigned long long Xd[KT * B];   // 8 KB  [k][b] dup
    int split = blockIdx.x, jt = blockIdx.y, tid = threadIdx.x;
    int s0, ns;
    if (split < 136) { s0 = split * 14; ns = 14; }
    else             { s0 = 1904 + (split - 136) * 12; ns = 12; }

    int jrow = tid >> 1;
    int kh = (tid & 1) * 4;                    // float4 idx 0..3 / 4..7 in stage row
    const float4* wrow4 = (const float4*)(W_ih + (size_t)(jt * JT + jrow) * KK);
    int bq = tid & 7, jq = tid >> 3;
    unsigned long long acc[2][4];
#pragma unroll
    for (int i = 0; i < 2; i++)
#pragma unroll
        for (int m = 0; m < 4; m++) acc[i][m] = 0ull;
    float2* Xd2 = (float2*)Xd;

    float4 f0, f1, f2, f3;
    float xr0, xr1, xr2, xr3;
    {
        const float4* ws = wrow4 + (size_t)s0 * 8 + kh;
        f0 = ws[0]; f1 = ws[1]; f2 = ws[2]; f3 = ws[3];
        const float* xs = g_xT + (size_t)s0 * KT * B;
        xr0 = xs[tid]; xr1 = xs[tid + 256]; xr2 = xs[tid + 512]; xr3 = xs[tid + 768];
    }

    for (int st = 0; st < ns; st++) {
        // commit current stage to smem
        {
            int kk = kh * 4;
            Ws[(kk + 0) * JT + jrow] = f0.x; Ws[(kk + 1) * JT + jrow] = f0.y;
            Ws[(kk + 2) * JT + jrow] = f0.z; Ws[(kk + 3) * JT + jrow] = f0.w;
            Ws[(kk + 4) * JT + jrow] = f1.x; Ws[(kk + 5) * JT + jrow] = f1.y;
            Ws[(kk + 6) * JT + jrow] = f1.z; Ws[(kk + 7) * JT + jrow] = f1.w;
            Ws[(kk + 8) * JT + jrow] = f2.x; Ws[(kk + 9) * JT + jrow] = f2.y;
            Ws[(kk + 10) * JT + jrow] = f2.z; Ws[(kk + 11) * JT + jrow] = f2.w;
            Ws[(kk + 12) * JT + jrow] = f3.x; Ws[(kk + 13) * JT + jrow] = f3.y;
            Ws[(kk + 14) * JT + jrow] = f3.z; Ws[(kk + 15) * JT + jrow] = f3.w;
            Xd2[tid] = make_float2(xr0, xr0);
            Xd2[tid + 256] = make_float2(xr1, xr1);
            Xd2[tid + 512] = make_float2(xr2, xr2);
            Xd2[tid + 768] = make_float2(xr3, xr3);
        }
        __syncthreads();
        // prefetch next stage into regs (LDGs hidden behind 32 k-iters of FMA)
        if (st + 1 < ns) {
            int g = s0 + st + 1;
            const float4* ws = wrow4 + (size_t)g * 8 + kh;
            f0 = ws[0]; f1 = ws[1]; f2 = ws[2]; f3 = ws[3];
            const float* xs = g_xT + (size_t)g * KT * B;
            xr0 = xs[tid]; xr1 = xs[tid + 256]; xr2 = xs[tid + 512]; xr3 = xs[tid + 768];
        }
#pragma unroll
        for (int k = 0; k < KT; k++) {
            ulonglong2 w2 = *(const ulonglong2*)(Ws + k * JT + jq * 4);
            ulonglong2 xa = *(const ulonglong2*)(Xd + k * B + bq * 4);
            ulonglong2 xb = *(const ulonglong2*)(Xd + k * B + bq * 4 + 2);
            ffma2(acc[0][0], w2.x, xa.x); ffma2(acc[1][0], w2.y, xa.x);
            ffma2(acc[0][1], w2.x, xa.y); ffma2(acc[1][1], w2.y, xa.y);
            ffma2(acc[0][2], w2.x, xb.x); ffma2(acc[1][2], w2.y, xb.x);
            ffma2(acc[0][3], w2.x, xb.y); ffma2(acc[1][3], w2.y, xb.y);
        }
        __syncthreads();
    }
    // acc[0][bi] = (j0,j1), acc[1][bi] = (j2,j3) for j = jt*128 + jq*4 + jj
    // store b-major: partial[split][j][b], b = bq*4 + bi
    float* pout = g_partial + ((size_t)split * G4 + jt * JT + jq * 4) * B + bq * 4;
#pragma unroll
    for (int jj = 0; jj < 4; jj++) {
        float v0, v1, v2, v3;
        if (jj == 0) { v0 = ((float2*)&acc[0][0])->x; v1 = ((float2*)&acc[0][1])->x; v2 = ((float2*)&acc[0][2])->x; v3 = ((float2*)&acc[0][3])->x; }
        else if (jj == 1) { v0 = ((float2*)&acc[0][0])->y; v1 = ((float2*)&acc[0][1])->y; v2 = ((float2*)&acc[0][2])->y; v3 = ((float2*)&acc[0][3])->y; }
        else if (jj == 2) { v0 = ((float2*)&acc[1][0])->x; v1 = ((float2*)&acc[1][1])->x; v2 = ((float2*)&acc[1][2])->x; v3 = ((float2*)&acc[1][3])->x; }
        else { v0 = ((float2*)&acc[1][0])->y; v1 = ((float2*)&acc[1][1])->y; v2 = ((float2*)&acc[1][2])->y; v3 = ((float2*)&acc[1][3])->y; }
        *(float4*)(pout + (size_t)jj * B) = make_float4(v0, v1, v2, v3);
    }
}

// ============================================================
// F: reduce partials + W_hh term + LSTM. grid (B,4) x 128 thr.
// partial[s][j][b] is L2-resident when this runs; scattered reads cost
// bounded L2 traffic only.
// ============================================================
__global__ __launch_bounds__(128) void k_final(const float* __restrict__ h_ak,
                                               const float* __restrict__ hidden,
                                               const float* __restrict__ W_hh,
                                               const float* __restrict__ b_ih,
                                               const float* __restrict__ b_hh,
                                               float* __restrict__ out) {
    __shared__ float ha[H];
    __shared__ float gs[128];
    int b = blockIdx.x, q = blockIdx.y, t = threadIdx.x;
    int gate = t >> 5, lane = t & 31;
    int hh = q * 32 + lane;
    int j = gate * H + hh;
    ha[t] = h_ak[b * H + t];
    __syncthreads();
    const float* pp = g_partial + (size_t)j * B + b;   // + s*G4*B per split
    float g = b_ih[j] + b_hh[j];
    float a0 = 0.f, a1 = 0.f, a2 = 0.f, a3 = 0.f;
    float a4 = 0.f, a5 = 0.f, a6 = 0.f, a7 = 0.f;
#pragma unroll 2
    for (int s = 0; s < 144; s += 8) {
        a0 += pp[(size_t)(s + 0) * G4 * B];
        a1 += pp[(size_t)(s + 1) * G4 * B];
        a2 += pp[(size_t)(s + 2) * G4 * B];
        a3 += pp[(size_t)(s + 3) * G4 * B];
        a4 += pp[(size_t)(s + 4) * G4 * B];
        a5 += pp[(size_t)(s + 5) * G4 * B];
        a6 += pp[(size_t)(s + 6) * G4 * B];
        a7 += pp[(size_t)(s + 7) * G4 * B];
    }
    a0 += pp[(size_t)144 * G4 * B];
    a1 += pp[(size_t)145 * G4 * B];
    a2 += pp[(size_t)146 * G4 * B];
    a3 += pp[(size_t)147 * G4 * B];
    g += ((a0 + a1) + (a2 + a3)) + ((a4 + a5) + (a6 + a7));
    const float4* wh = (const float4*)(W_hh + (size_t)j * H);
#pragma unroll
    for (int r = 0; r < H / 4; r++) {
        float4 w = wh[r];
        g += w.x * ha[4 * r] + w.y * ha[4 * r + 1] + w.z * ha[4 * r + 2] + w.w * ha[4 * r + 3];
    }
    gs[t] = g;
    __syncthreads();
    if (t < 32) {
        float gi = gs[t], gf = gs[32 + t], gg = gs[64 + t], go = gs[96 + t];
        int h = q * 32 + t;
        float c = sigm(gf) * hidden[b * H + h] + sigm(gi) * tanhf(gg);
        float hn = sigm(go) * tanhf(c);
        out[b * H + h] = hn;            // h_new
        out[B * H + b * H + h] = c;     // c_new
    }
}

// ============================================================
extern "C" void kernel_launch(void* const* d_in, const int* in_sizes, int n_in,
                              void* d_out, int out_size) {
    const float* h_ak   = (const float*)d_in[0];
    const float* H_r    = (const float*)d_in[1];
    const float* hidden = (const float*)d_in[2];
    const float* W_f    = (const float*)d_in[3];
    const float* b_f    = (const float*)d_in[4];
    const float* W_fn   = (const float*)d_in[5];
    const float* beta_w = (const float*)d_in[6];
    const float* beta_b = (const float*)d_in[7];
    const float* W_ih   = (const float*)d_in[8];
    const float* W_hh   = (const float*)d_in[9];
    const float* b_ih   = (const float*)d_in[10];
    const float* b_hh   = (const float*)d_in[11];
    float* out = (float*)d_out;

    cudaFuncSetAttribute(k_scores, cudaFuncAttributeMaxDynamicSharedMemorySize, A1_SMEM);

    k_prep<<<48, 128>>>(h_ak, W_f, b_f, W_fn);
    k_scores<<<256, 128, A1_SMEM>>>(H_r, beta_w, beta_b);
    k_softmax<<<B, P>>>(out + 2 * B * H);
    k_buildx<<<P, 256>>>(H_r);
    k_gemm<<<dim3(SPLITS, 4), 256>>>(W_ih);
    k_final<<<dim3(B, 4), 128>>>(h_ak, hidden, W_hh, b_ih, b_hh, out);
    (void)in_sizes; (void)n_in; (void)out_size;
}